// round 12
// baseline (speedup 1.0000x reference)
#include <cuda_runtime.h>
#include <math.h>

#define IGNORE_LABEL (-100LL)
#define MAXB 64
#define MAXROWS 16384

// zero at module load; every scratch slot is reset by its consumer,
// so each launch / graph replay starts from zeroed scratch.
__device__ double g_tasksum[MAXB];
__device__ int    g_correct[MAXB];
__device__ int    g_valid[MAXB];
__device__ int    g_labels_is64;
__device__ unsigned int g_done;
// per-row cross-block combine scratch
__device__ float        g_rsum[MAXROWS];   // fp32 sum of 2 partials (commutative -> deterministic)
__device__ unsigned int g_rmax[MAXROWS];   // order-encoded float max; 0 == "-inf"
__device__ unsigned int g_rcnt[MAXROWS];   // per-row arrival ticket

__device__ __forceinline__ float frcp_fast(float t) {
    float r;
    asm("rcp.approx.ftz.f32 %0, %1;" : "=f"(r) : "f"(t));
    return r;
}

__device__ __forceinline__ float smap(float v) {
    // s(x) = x<0 ? 1/(1-x) : x+1
    float r = frcp_fast(1.0f - v);
    return v < 0.0f ? r : v + 1.0f;
}

// monotonic float<->uint encoding: encode(a) < encode(b) iff a < b; 0 < encode(any float)
__device__ __forceinline__ unsigned int fenc(float f) {
    unsigned int u = __float_as_uint(f);
    return (u & 0x80000000u) ? ~u : (u | 0x80000000u);
}
__device__ __forceinline__ float fdec(unsigned int u) {
    unsigned int v = (u & 0x80000000u) ? (u & 0x7FFFFFFFu) : ~u;
    return __uint_as_float(v);
}

// tiny: decide whether labels buffer is int64 or int32.
__global__ void probe_kernel(const void* __restrict__ labels, int V) {
    long long v = ((const long long*)labels)[threadIdx.x];
    bool okv = (v >= 0 && v < (long long)V) || v == IGNORE_LABEL;
    unsigned m = __ballot_sync(0xffffffffu, okv);
    if (threadIdx.x == 0) g_labels_is64 = (m == 0xffffffffu);
}

// two blocks per token row (one per half). The second half-block to finish a
// row runs that row's epilogue; the globally-last block computes the loss.
__global__ void __launch_bounds__(256) row_kernel(
        const float* __restrict__ logits,
        const void* __restrict__ labels_raw,
        const float* __restrict__ qh,
        const float* __restrict__ qc,
        float* __restrict__ out,
        int V, int Lseq, int Bn) {
    const int tid  = threadIdx.x;
    const int nt   = blockDim.x;
    const int lane = tid & 31;
    const int wid  = tid >> 5;
    const int row  = blockIdx.x >> 1;
    const int half = blockIdx.x & 1;
    const float* __restrict__ x = logits + (size_t)row * V;

    const int Vh = V >> 1;
    const int lo = half ? Vh : 0;
    const int hi = half ? V  : Vh;

    __shared__ float wsum[8];
    __shared__ float wmax[8];
    __shared__ float smaxv[256];
    __shared__ int   sidx[256];
    __shared__ int   sh_do_epi;
    __shared__ int   sh_need;
    __shared__ long long sh_label;

    // ---- scan [lo, hi): scalar head to 16B alignment, float4 body, scalar tail ----
    float sumA = 0.f, sumB = 0.f;
    float vmax = -INFINITY;

    const int head = (lo + 3) & ~3;           // first 4-aligned element >= lo
    for (int i = lo + tid; i < head && i < hi; i += nt) {
        float v = __ldcs(&x[i]);
        sumA += smap(v);
        vmax = fmaxf(vmax, v);
    }
    const int n4lo = head >> 2;
    const int n4hi = hi >> 2;
    const float4* __restrict__ x4 = (const float4*)x;
    #pragma unroll 4
    for (int i = n4lo + tid; i < n4hi; i += nt) {
        float4 v = __ldcs(&x4[i]);
        sumA += smap(v.x) + smap(v.y);
        sumB += smap(v.z) + smap(v.w);
        vmax = fmaxf(vmax, fmaxf(fmaxf(v.x, v.y), fmaxf(v.z, v.w)));
    }
    for (int i = (n4hi << 2) + tid; i < hi; i += nt) {
        float v = __ldcs(&x[i]);
        sumA += smap(v);
        vmax = fmaxf(vmax, v);
    }

    // ---- warp reduce + cross-warp combine ----
    float ws = sumA + sumB;
    #pragma unroll
    for (int o = 16; o > 0; o >>= 1) {
        ws   += __shfl_down_sync(0xffffffffu, ws, o);
        vmax  = fmaxf(vmax, __shfl_down_sync(0xffffffffu, vmax, o));
    }
    if (lane == 0) { wsum[wid] = ws; wmax[wid] = vmax; }
    __syncthreads();

    if (tid == 0) {
        float rs = wsum[0], rm = wmax[0];
        #pragma unroll
        for (int w = 1; w < 8; w++) { rs += wsum[w]; rm = fmaxf(rm, wmax[w]); }
        atomicAdd(&g_rsum[row], rs);
        atomicMax(&g_rmax[row], fenc(rm));
        __threadfence();
        unsigned int t = atomicAdd(&g_rcnt[row], 1u);
        sh_do_epi = (t == 1u);      // second half-block finishes the row
        sh_need = 0;
    }
    __syncthreads();

    if (sh_do_epi) {
        // ---- row epilogue ----
        if (tid == 0) {
            float rowsum = *((volatile float*)&g_rsum[row]);
            float rowmax = fdec(*((volatile unsigned int*)&g_rmax[row]));

            long long label;
            if (g_labels_is64) label = ((const long long*)labels_raw)[row];
            else               label = (long long)((const int*)labels_raw)[row];
            sh_label = label;

            if (label >= 0 && label < (long long)V) {
                int b = row / Lseq;
                double xd = (double)x[(int)label];
                double sl = xd < 0.0 ? 1.0 / (1.0 - xd + 1e-30) : xd + 1.0;
                double pt = log((double)rowsum) - log(sl);   // -log(s_label/sum)
                atomicAdd(&g_tasksum[b], pt);
                atomicAdd(&g_valid[b], 1);
                if ((float)x[(int)label] == rowmax) sh_need = 1;
            }
            // reset per-row scratch for next launch / graph replay
            g_rsum[row] = 0.f;
            g_rmax[row] = 0u;
            g_rcnt[row] = 0u;
        }
        __syncthreads();

        if (sh_need) {
            // rare: exact first-index argmax over the FULL row
            const int V4 = V >> 2;
            float lmax = -INFINITY;
            int   lidx = 0x7fffffff;
            for (int k = tid; k < V4; k += nt) {
                float4 v = __ldg(&x4[k]);
                int base = k << 2;
                if (v.x > lmax) { lmax = v.x; lidx = base + 0; }
                if (v.y > lmax) { lmax = v.y; lidx = base + 1; }
                if (v.z > lmax) { lmax = v.z; lidx = base + 2; }
                if (v.w > lmax) { lmax = v.w; lidx = base + 3; }
            }
            for (int k = (V4 << 2) + tid; k < V; k += nt) {
                float v = __ldg(&x[k]);
                if (v > lmax) { lmax = v; lidx = k; }
            }
            smaxv[tid] = lmax;
            sidx[tid]  = lidx;
            __syncthreads();
            for (int s = nt >> 1; s > 0; s >>= 1) {
                if (tid < s) {
                    float mv = smaxv[tid + s]; int mi = sidx[tid + s];
                    if (mv > smaxv[tid] || (mv == smaxv[tid] && mi < sidx[tid])) {
                        smaxv[tid] = mv; sidx[tid] = mi;
                    }
                }
                __syncthreads();
            }
            if (tid == 0 && (long long)sidx[0] == sh_label) {
                atomicAdd(&g_correct[row / Lseq], 1);
            }
        }
    }

    // ---- globally-last block computes the final loss ----
    if (tid == 0) {
        __threadfence();
        unsigned int ticket = atomicAdd(&g_done, 1u);
        if (ticket == gridDim.x - 1) {
            volatile double* vsum = g_tasksum;
            volatile int*    vval = g_valid;
            volatile int*    vcor = g_correct;
            float Ltask = 0.f, lh = 0.f, lc = 0.f;
            for (int b = 0; b < Bn; b++) {
                int    nv = vval[b];
                int    nc = vcor[b];
                double ts = vsum[b];
                float cnt = (float)(nv > 1 ? nv : 1);
                Ltask += (float)ts / cnt;
                float t = (nc == nv) ? 1.f : 0.f;
                float xh = qh[b];
                lh += fmaxf(xh, 0.f) - xh * t + log1pf(expf(-fabsf(xh)));
                float tc = 1.f / (1.f + expf(-xh));
                float xc = qc[b];
                lc += fmaxf(xc, 0.f) - xc * tc + log1pf(expf(-fabsf(xc)));
                vsum[b] = 0.0;
                vval[b] = 0;
                vcor[b] = 0;
            }
            Ltask /= (float)Bn;
            float Lhalt = 0.5f * (lh / (float)Bn + lc / (float)Bn);
            out[0] = Ltask + Lhalt;
            __threadfence();
            g_done = 0;
        }
    }
}

extern "C" void kernel_launch(void* const* d_in, const int* in_sizes, int n_in,
                              void* d_out, int out_size) {
    // Identify inputs by size, not position.
    int li = 0;
    for (int i = 1; i < n_in; i++) if (in_sizes[i] > in_sizes[li]) li = i;
    int lab = -1;
    for (int i = 0; i < n_in; i++) {
        if (i == li) continue;
        if (lab < 0 || in_sizes[i] > in_sizes[lab]) lab = i;
    }
    int qi[2]; int nq = 0;
    for (int i = 0; i < n_in && nq < 2; i++) {
        if (i != li && i != lab) qi[nq++] = i;
    }

    const float* logits = (const float*)d_in[li];
    const void*  labels = d_in[lab];
    const float* qh     = (const float*)d_in[qi[0]];
    const float* qc     = (const float*)d_in[qi[1]];

    const int Bn   = in_sizes[qi[0]];
    const int rows = in_sizes[lab];
    const int Lseq = rows / Bn;
    const int V    = (int)((long long)in_sizes[li] / rows);

    probe_kernel<<<1, 32>>>(labels, V);
    row_kernel<<<rows * 2, 256>>>(logits, labels, qh, qc, (float*)d_out,
                                  V, Lseq, Bn);
}

// round 13
// speedup vs baseline: 1.2084x; 1.2084x over previous
#include <cuda_runtime.h>
#include <math.h>

#define IGNORE_LABEL (-100LL)
#define MAXB 64

// zero at module load; the finalizing block resets everything after use,
// so each launch / graph replay starts from zeroed scratch.
__device__ double g_tasksum[MAXB];
__device__ int    g_correct[MAXB];
__device__ int    g_valid[MAXB];
__device__ int    g_labels_is64;
__device__ unsigned int g_done;

__device__ __forceinline__ float frcp_fast(float t) {
    float r;
    asm("rcp.approx.ftz.f32 %0, %1;" : "=f"(r) : "f"(t));
    return r;
}

__device__ __forceinline__ float smap(float v) {
    // s(x) = x<0 ? 1/(1-x) : x+1
    float r = frcp_fast(1.0f - v);
    return v < 0.0f ? r : v + 1.0f;
}

// tiny: decide whether labels buffer is int64 or int32.
__global__ void probe_kernel(const void* __restrict__ labels, int V) {
    long long v = ((const long long*)labels)[threadIdx.x];
    bool okv = (v >= 0 && v < (long long)V) || v == IGNORE_LABEL;
    unsigned m = __ballot_sync(0xffffffffu, okv);
    if (threadIdx.x == 0) g_labels_is64 = (m == 0xffffffffu);
}

// one block per token row; the last block to finish also computes the final loss.
// 28KB smem pad caps residency at 7 blocks/SM (7*148=1036 concurrent):
// 4096/1036 = 3.95 waves -> 98.8% slot efficiency vs 86.5% at 8 blocks/SM.
__global__ void __launch_bounds__(256, 7) row_kernel(
        const float* __restrict__ logits,
        const void* __restrict__ labels_raw,
        const float* __restrict__ qh,
        const float* __restrict__ qc,
        float* __restrict__ out,
        int V, int Lseq, int Bn) {
    const int row = blockIdx.x;
    const int tid = threadIdx.x;
    const int nt  = blockDim.x;
    const int lane = tid & 31;
    const int wid  = tid >> 5;
    const float* __restrict__ x = logits + (size_t)row * V;

    __shared__ char  s_pad[28 * 1024];   // occupancy limiter (7 blocks/SM)
    __shared__ float wsum[8];
    __shared__ float wmax[8];
    __shared__ float smaxv[256];
    __shared__ int   sidx[256];
    __shared__ int   sh_need_scan;
    __shared__ float sh_sum;
    __shared__ float sh_max;

    // opaque touch so the pad is not eliminated (V >= 1 always at runtime)
    if (V < 0) s_pad[0] = (char)tid;

    // ---- scan starts immediately: no label read, no syncthreads up front ----
    float sumA = 0.f, sumB = 0.f;
    float vmax = -INFINITY;

    const int V4 = V >> 2;
    const float4* __restrict__ x4 = (const float4*)x;
    #pragma unroll 4
    for (int i = tid; i < V4; i += nt) {
        float4 v = __ldcs(&x4[i]);      // streaming: evict-first
        sumA += smap(v.x) + smap(v.y);
        sumB += smap(v.z) + smap(v.w);
        vmax = fmaxf(vmax, fmaxf(fmaxf(v.x, v.y), fmaxf(v.z, v.w)));
    }
    for (int i = (V4 << 2) + tid; i < V; i += nt) {
        float v = __ldcs(&x[i]);
        sumA += smap(v);
        vmax = fmaxf(vmax, v);
    }

    // ---- warp-shuffle reduce, then tiny cross-warp combine ----
    float wsumv = sumA + sumB;
    #pragma unroll
    for (int o = 16; o > 0; o >>= 1) {
        wsumv += __shfl_down_sync(0xffffffffu, wsumv, o);
        vmax   = fmaxf(vmax, __shfl_down_sync(0xffffffffu, vmax, o));
    }
    if (lane == 0) { wsum[wid] = wsumv; wmax[wid] = vmax; }
    __syncthreads();

    if (tid == 0) {
        float rs = wsum[0], rm = wmax[0];
        #pragma unroll
        for (int w = 1; w < 8; w++) { rs += wsum[w]; rm = fmaxf(rm, wmax[w]); }
        sh_sum = rs;
        sh_max = rm;

        long long label;
        if (g_labels_is64) label = ((const long long*)labels_raw)[row];
        else               label = (long long)((const int*)labels_raw)[row];
        int need = 0;
        if (label >= 0 && label < (long long)V) {
            float xl = x[(int)label];
            if (xl == rm) need = 1;      // label attains row max -> exact argmax
        }
        sh_need_scan = need;
    }
    __syncthreads();

    int arg_idx = -1;
    if (sh_need_scan) {
        // rare second pass: exact first-index argmax
        float lmax = -INFINITY;
        int   lidx = 0x7fffffff;
        for (int k = tid; k < V4; k += nt) {
            float4 v = __ldg(&x4[k]);
            int base = k << 2;
            if (v.x > lmax) { lmax = v.x; lidx = base + 0; }
            if (v.y > lmax) { lmax = v.y; lidx = base + 1; }
            if (v.z > lmax) { lmax = v.z; lidx = base + 2; }
            if (v.w > lmax) { lmax = v.w; lidx = base + 3; }
        }
        for (int k = (V4 << 2) + tid; k < V; k += nt) {
            float v = __ldg(&x[k]);
            if (v > lmax) { lmax = v; lidx = k; }
        }
        smaxv[tid] = lmax;
        sidx[tid]  = lidx;
        __syncthreads();
        for (int s = nt >> 1; s > 0; s >>= 1) {
            if (tid < s) {
                float mv = smaxv[tid + s]; int mi = sidx[tid + s];
                if (mv > smaxv[tid] || (mv == smaxv[tid] && mi < sidx[tid])) {
                    smaxv[tid] = mv; sidx[tid] = mi;
                }
            }
            __syncthreads();
        }
        arg_idx = sidx[0];
    }

    if (tid == 0) {
        long long label;
        if (g_labels_is64) label = ((const long long*)labels_raw)[row];
        else               label = (long long)((const int*)labels_raw)[row];

        if (label >= 0 && label < (long long)V) {
            int b = row / Lseq;
            double xd = (double)x[(int)label];
            double sl = xd < 0.0 ? 1.0 / (1.0 - xd + 1e-30) : xd + 1.0;
            double pt = log((double)sh_sum) - log(sl);   // -log(s_label/sum)
            atomicAdd(&g_tasksum[b], pt);
            atomicAdd(&g_valid[b], 1);
            bool correct = sh_need_scan && ((long long)arg_idx == label);
            if (correct) atomicAdd(&g_correct[b], 1);
        }

        // ---- last-block finalize ----
        __threadfence();
        unsigned int ticket = atomicAdd(&g_done, 1u);
        if (ticket == gridDim.x - 1) {
            volatile double* vsum = g_tasksum;
            volatile int*    vval = g_valid;
            volatile int*    vcor = g_correct;
            float Ltask = 0.f, lh = 0.f, lc = 0.f;
            for (int b = 0; b < Bn; b++) {
                int    nv = vval[b];
                int    nc = vcor[b];
                double ts = vsum[b];
                float cnt = (float)(nv > 1 ? nv : 1);
                Ltask += (float)ts / cnt;
                float t = (nc == nv) ? 1.f : 0.f;
                float xh = qh[b];
                lh += fmaxf(xh, 0.f) - xh * t + log1pf(expf(-fabsf(xh)));
                float tc = 1.f / (1.f + expf(-xh));
                float xc = qc[b];
                lc += fmaxf(xc, 0.f) - xc * tc + log1pf(expf(-fabsf(xc)));
                vsum[b] = 0.0;
                vval[b] = 0;
                vcor[b] = 0;
            }
            Ltask /= (float)Bn;
            float Lhalt = 0.5f * (lh / (float)Bn + lc / (float)Bn);
            out[0] = Ltask + Lhalt;
            __threadfence();
            g_done = 0;
        }
    }
}

extern "C" void kernel_launch(void* const* d_in, const int* in_sizes, int n_in,
                              void* d_out, int out_size) {
    // Identify inputs by size, not position.
    int li = 0;
    for (int i = 1; i < n_in; i++) if (in_sizes[i] > in_sizes[li]) li = i;
    int lab = -1;
    for (int i = 0; i < n_in; i++) {
        if (i == li) continue;
        if (lab < 0 || in_sizes[i] > in_sizes[lab]) lab = i;
    }
    int qi[2]; int nq = 0;
    for (int i = 0; i < n_in && nq < 2; i++) {
        if (i != li && i != lab) qi[nq++] = i;
    }

    const float* logits = (const float*)d_in[li];
    const void*  labels = d_in[lab];
    const float* qh     = (const float*)d_in[qi[0]];
    const float* qc     = (const float*)d_in[qi[1]];

    const int Bn   = in_sizes[qi[0]];
    const int rows = in_sizes[lab];
    const int Lseq = rows / Bn;
    const int V    = (int)((long long)in_sizes[li] / rows);

    probe_kernel<<<1, 32>>>(labels, V);
    row_kernel<<<rows, 256>>>(logits, labels, qh, qc, (float*)d_out, V, Lseq, Bn);
}